// round 17
// baseline (speedup 1.0000x reference)
#include <cuda_runtime.h>
#include <cstdint>

// GumbelSinkhorn: B=128, N=512 rows, M=512 cols, tau=1, 5 iters.
// ONE persistent kernel: global work queue (stage-major), per-(stage,batch)
// ready flags with release/acquire. Stages t=0..4 = fused softmax pairs,
// stage 5 = final axis-1 multiply + masked full-coverage output. Compact E
// slabs (row stride ceil128(nt)). All mutable global data via .cg (L2-only).
// FIX (r16): the misaligned access was the SHARED array -- adding s_idx next
// to sm[] shifted sm off 16B alignment; both are now explicitly __align__(16).

#define BB 128
#define NN 512
#define MM 512
#define LOG2E 1.4426950408889634f
#define NCTAS 592

__device__ __align__(16) float    g_E[(size_t)BB * NN * MM];
__device__ __align__(16) float    g_acc[5][BB * MM];
__device__ __align__(16) float    g_ics[5][BB * MM];
__device__ __align__(16) float    g_scale0[MM];     // LOG2E broadcast (t=0)
__device__ unsigned g_done[5][BB];
__device__ unsigned g_ready[5][BB];
__device__ int      g_items[BB * 32];               // (b<<5)|strip
__device__ int      g_ebase[BB];
__device__ int      g_cnt;
__device__ unsigned g_work;

__device__ __forceinline__ float ex2f(float x) {
    float y;
    asm("ex2.approx.f32 %0, %1;" : "=f"(y) : "f"(x));
    return y;
}
__device__ __forceinline__ unsigned atom_inc_acqrel(unsigned* p) {
    unsigned old;
    asm volatile("atom.add.acq_rel.gpu.global.u32 %0, [%1], 1;"
                 : "=r"(old) : "l"(p) : "memory");
    return old;
}
__device__ __forceinline__ float ld_cg(const float* p) {
    float v;
    asm volatile("ld.global.cg.f32 %0, [%1];" : "=f"(v) : "l"(p));
    return v;
}
__device__ __forceinline__ float4 ldcg4(const float* p) {
    float4 v;
    asm volatile("ld.global.cg.v4.f32 {%0,%1,%2,%3}, [%4];"
                 : "=f"(v.x), "=f"(v.y), "=f"(v.z), "=f"(v.w) : "l"(p));
    return v;
}
__device__ __forceinline__ void stcs4(float* p, float4 v) {
    asm volatile("st.global.cs.v4.f32 [%0], {%1,%2,%3,%4};"
                 :: "l"(p), "f"(v.x), "f"(v.y), "f"(v.z), "f"(v.w) : "memory");
}
__device__ __forceinline__ float warp_sum(float v) {
    v += __shfl_xor_sync(0xffffffffu, v, 16);
    v += __shfl_xor_sync(0xffffffffu, v, 8);
    v += __shfl_xor_sync(0xffffffffu, v, 4);
    v += __shfl_xor_sync(0xffffffffu, v, 2);
    v += __shfl_xor_sync(0xffffffffu, v, 1);
    return v;
}

// ---------------------------------------------------------------------------
__global__ void setup_kernel(const int* __restrict__ fa,
                             const int* __restrict__ ta) {
    float4* p = (float4*)&g_acc[0][0];
    int total4 = 5 * BB * MM / 4;
    int gid = blockIdx.x * blockDim.x + threadIdx.x;
    for (int i = gid; i < total4; i += gridDim.x * blockDim.x)
        p[i] = make_float4(0.f, 0.f, 0.f, 0.f);
    if (gid < 5 * BB) (&g_done[0][0])[gid] = 0u;
    if (gid >= 1024 && gid < 1024 + 5 * BB) (&g_ready[0][0])[gid - 1024] = 0u;
    if (gid < MM) g_scale0[gid] = LOG2E;
    if (gid == 2048) g_work = 0u;

    if (blockIdx.x == 0 && threadIdx.x < 32) {
        int lane = threadIdx.x;
        int carryI = 0, carryE = 0;
        for (int g = 0; g < 4; g++) {
            int b = g * 32 + lane;
            int na = fa[b], nt = ta[b];
            bool act = (na > 0) && (nt > 0);
            int strips = act ? (na + 15) >> 4 : 0;
            int ntup   = act ? ((nt + 127) & ~127) : 0;
            int esz    = strips * 16 * ntup;
            int incI = strips, incE = esz;
            #pragma unroll
            for (int d = 1; d < 32; d <<= 1) {
                int tI = __shfl_up_sync(0xffffffffu, incI, d);
                int tE = __shfl_up_sync(0xffffffffu, incE, d);
                if (lane >= d) { incI += tI; incE += tE; }
            }
            int offI = carryI + incI - strips;
            g_ebase[b] = carryE + incE - esz;
            for (int s = 0; s < strips; s++) g_items[offI + s] = (b << 5) | s;
            carryI += __shfl_sync(0xffffffffu, incI, 31);
            carryE += __shfl_sync(0xffffffffu, incE, 31);
        }
        if (lane == 0) g_cnt = carryI;
    }
}

// ---------------------------------------------------------------------------
__device__ __forceinline__ void wait_ready(int stage, int b, int tid) {
    if (tid == 0) {
        const unsigned* f = &g_ready[stage][b];
        unsigned r;
        asm volatile("ld.acquire.gpu.global.u32 %0, [%1];" : "=r"(r) : "l"(f));
        while (!r) {
            __nanosleep(64);
            asm volatile("ld.acquire.gpu.global.u32 %0, [%1];" : "=r"(r) : "l"(f));
        }
    }
    __syncthreads();
}

// Tail: column partials + atomics; last finisher inverts colsums and
// release-publishes the stage ready flag for this batch.
__device__ __forceinline__ void col_tail(float (*sm)[MM], int stage, float factor,
                                         int b, int na, int nt, int tid) {
    __syncthreads();
    if (tid < nt) {
        float s = 0.f;
        #pragma unroll
        for (int ww = 0; ww < 16; ww++) s += sm[ww][tid];
        atomicAdd(&g_acc[stage][b * MM + tid], s);
    }
    __syncthreads();
    __shared__ bool last;
    if (tid == 0) {
        unsigned items = (unsigned)((na + 15) >> 4);
        last = (atom_inc_acqrel(&g_done[stage][b]) == items - 1u);
    }
    __syncthreads();
    if (last) {
        float ssum = ld_cg(&g_acc[stage][b * MM + tid]);
        g_ics[stage][b * MM + tid] = (ssum > 0.f) ? __fdividef(factor, ssum) : 0.f;
    }
    __syncthreads();
    if (last && tid == 0)
        asm volatile("st.release.gpu.global.u32 [%0], %1;"
                     :: "l"(&g_ready[stage][b]), "r"(1u) : "memory");
}

// ---------------------------------------------------------------------------
__global__ void __launch_bounds__(512) sinkhorn_kernel(
        const float* __restrict__ logits,
        float* __restrict__ out,
        const int* __restrict__ fa, const int* __restrict__ ta) {
    __shared__ __align__(16) float sm[16][MM];
    __shared__ __align__(16) unsigned s_idx;
    int tid = threadIdx.x, w = tid >> 5, lane = tid & 31;
    unsigned cnt = (unsigned)g_cnt;
    unsigned compute_total = 5u * cnt;
    unsigned total = compute_total + BB * 32u;

    for (;;) {
        if (tid == 0) s_idx = atomicAdd(&g_work, 1u);
        __syncthreads();
        unsigned idx = s_idx;
        __syncthreads();                    // tid0 may rewrite s_idx next iter
        if (idx >= total) return;

        if (idx < compute_total) {
            // ---------------- compute item: stage t, fused softmax pair ----
            int t = (int)(idx / cnt);
            int item = g_items[idx - (unsigned)t * cnt];
            int b = item >> 5, s = item & 31;
            int na = fa[b], nt = ta[b];
            if (t > 0) wait_ready(t - 1, b, tid);

            int ntup = (nt + 127) & ~127;
            int gr = (s << 4) + w;
            bool rowv = (gr < na);
            float* Ew = g_E + g_ebase[b] + gr * ntup;
            const float* Sr = t ? (const float*)Ew
                                : logits + (size_t)b * NN * MM + (size_t)gr * MM;
            const float* CS = t ? &g_ics[t - 1][b * MM] : g_scale0;
            float factor = (t == 4) ? 1.0f : LOG2E;

            float4 v[4];
            float racc = 0.f;
            #pragma unroll
            for (int k = 0; k < 4; k++) {
                int cb = lane * 4 + k * 128;
                v[k] = make_float4(0.f, 0.f, 0.f, 0.f);
                if (rowv && cb < nt) {
                    float4 e  = ldcg4(Sr + cb);
                    float4 s4 = ldcg4(CS + cb);
                    v[k].x = ex2f(e.x * s4.x);
                    v[k].y = (cb + 1 < nt) ? ex2f(e.y * s4.y) : 0.f;
                    v[k].z = (cb + 2 < nt) ? ex2f(e.z * s4.z) : 0.f;
                    v[k].w = (cb + 3 < nt) ? ex2f(e.w * s4.w) : 0.f;
                    racc += (v[k].x + v[k].y) + (v[k].z + v[k].w);
                }
            }
            float rinv = __fdividef(LOG2E, warp_sum(racc));
            #pragma unroll
            for (int k = 0; k < 4; k++) {
                int cb = lane * 4 + k * 128;
                float4 o = make_float4(0.f, 0.f, 0.f, 0.f);
                if (rowv && cb < nt) {
                    o.x = ex2f(v[k].x * rinv);
                    o.y = (cb + 1 < nt) ? ex2f(v[k].y * rinv) : 0.f;
                    o.z = (cb + 2 < nt) ? ex2f(v[k].z * rinv) : 0.f;
                    o.w = (cb + 3 < nt) ? ex2f(v[k].w * rinv) : 0.f;
                    *(float4*)(Ew + cb) = o;
                }
                if (k * 128 < nt)
                    *(float4*)(&sm[w][cb]) = o;
            }
            col_tail(sm, t, factor, b, na, nt, tid);
        } else {
            // ---------------- final item: out = E9 * ics[4], masked --------
            unsigned fid = idx - compute_total;
            int b = (int)(fid >> 5), s = (int)(fid & 31u);
            int na = fa[b], nt = ta[b];
            bool act = (na > 0) && (nt > 0);
            if (act && (s << 4) < na) wait_ready(4, b, tid);

            int ntup = (nt + 127) & ~127;
            int gr = (s << 4) + w;
            bool rowv = act && (gr < na);
            const float* Er = g_E + g_ebase[b] + gr * ntup;
            const float* CS = &g_ics[4][b * MM];
            float* Ob = out + (size_t)b * NN * MM + (size_t)gr * MM;
            #pragma unroll
            for (int k = 0; k < 4; k++) {
                int cb = lane * 4 + k * 128;
                float4 o = make_float4(0.f, 0.f, 0.f, 0.f);
                if (rowv && cb < nt) {
                    float4 e  = ldcg4(Er + cb);
                    float4 s4 = ldcg4(CS + cb);
                    o.x = e.x * s4.x; o.y = e.y * s4.y;
                    o.z = e.z * s4.z; o.w = e.w * s4.w;
                }
                stcs4(Ob + cb, o);
            }
        }
    }
}

extern "C" void kernel_launch(void* const* d_in, const int* in_sizes, int n_in,
                              void* d_out, int out_size) {
    const float* logits = (const float*)d_in[0];
    const int*   fa     = (const int*)d_in[1];
    const int*   ta     = (const int*)d_in[2];
    float*       out    = (float*)d_out;

    setup_kernel<<<256, 256>>>(fa, ta);
    sinkhorn_kernel<<<NCTAS, 512>>>(logits, out, fa, ta);
}